// round 1
// baseline (speedup 1.0000x reference)
#include <cuda_runtime.h>
#include <math.h>
#include <stdint.h>

#define NB 32
#define NL 8400
#define NC 80
#define NGT 64
#define KTOP 13
#define FEPS 1e-9f
#define CEPS 1e-7f

// ---------------- device scratch (no dynamic allocation allowed) ----------------
__device__ float g_scores_t[(size_t)NB * NC * NL];         // transposed scores (B,C,L)
__device__ float g_iou[(size_t)NB * NGT * NL];             // masked iou (pad*in_gts applied)
__device__ float g_metric[(size_t)NB * NGT * NL];          // alignment metric
__device__ unsigned char g_ingts[(size_t)NB * NGT * NL];   // is_in_gts
__device__ unsigned char g_mask[(size_t)NB * NGT * NL];    // mask_positive
__device__ int g_topk[NB * NGT * KTOP];
__device__ float g_rowmaxM[NB * NGT];
__device__ float g_rowmaxI[NB * NGT];
__device__ float g_norm[NB * NL];
__device__ int g_lab[NB * NL];

// ---------------- kernel 0: transpose pred_scores (B,L,C) -> (B,C,L) ----------------
__global__ void k_transpose(const float* __restrict__ ps) {
    __shared__ float tile[32][33];
    int b = blockIdx.z;
    int j0 = blockIdx.x * 32;
    int c0 = blockIdx.y * 32;
    int tx = threadIdx.x, ty = threadIdx.y;
    int j = j0 + ty, c = c0 + tx;
    if (j < NL && c < NC)
        tile[ty][tx] = ps[((size_t)b * NL + j) * NC + c];
    __syncthreads();
    int c2 = c0 + ty, j2 = j0 + tx;
    if (c2 < NC && j2 < NL)
        g_scores_t[((size_t)b * NC + c2) * NL + j2] = tile[tx][ty];
}

// ---------------- kernel 1: per-pair iou / metric / in_gts; zero mask ----------------
__global__ void k_pair(const float* __restrict__ pred_bboxes,
                       const float* __restrict__ centers,
                       const int* __restrict__ gt_labels,
                       const float* __restrict__ gt_bboxes,
                       const float* __restrict__ pad) {
    int b = blockIdx.z;
    int i = blockIdx.y;
    int j = blockIdx.x * blockDim.x + threadIdx.x;
    if (j >= NL) return;
    int gt = b * NGT + i;
    size_t o = (size_t)gt * NL + j;

    g_mask[o] = 0;
    float padv = pad[gt];
    if (padv == 0.f) {
        g_iou[o] = 0.f; g_metric[o] = 0.f; g_ingts[o] = 0;
        return;
    }

    float4 gb = ((const float4*)gt_bboxes)[gt];
    int lab = gt_labels[gt];

    float2 ct = ((const float2*)centers)[j];
    float x = ct.x, y = ct.y;
    float lt = fminf(fminf(x - gb.x, y - gb.y), fminf(gb.z - x, gb.w - y));
    float ingts = (lt > FEPS) ? 1.f : 0.f;

    float4 pb = ((const float4*)pred_bboxes)[(size_t)b * NL + j];

    // CIoU(gt, pred)
    float a1 = (gb.z - gb.x) * (gb.w - gb.y);
    float a2 = (pb.z - pb.x) * (pb.w - pb.y);
    float iw = fminf(gb.z, pb.z) - fmaxf(gb.x, pb.x);
    float ih = fminf(gb.w, pb.w) - fmaxf(gb.y, pb.y);
    float inter = fmaxf(iw, 0.f) * fmaxf(ih, 0.f);
    float uni = a1 + a2 - inter;
    float iou = inter / uni;
    float cw = fmaxf(gb.z, pb.z) - fminf(gb.x, pb.x);
    float ch = fmaxf(gb.w, pb.w) - fminf(gb.y, pb.y);
    cw = fmaxf(cw, 0.f); ch = fmaxf(ch, 0.f);
    float diag2 = cw * cw + ch * ch + CEPS;
    float dx = (gb.x + gb.z) * 0.5f - (pb.x + pb.z) * 0.5f;
    float dy = (gb.y + gb.w) * 0.5f - (pb.y + pb.w) * 0.5f;
    float dist2 = dx * dx + dy * dy;
    float diou = iou - dist2 / diag2;
    float w1 = gb.z - gb.x, h1 = gb.w - gb.y;
    float w2 = pb.z - pb.x, h2 = pb.w - pb.y;
    const float c4pi2 = 4.0f / (float)(M_PI * M_PI);
    float dv = atanf(w1 / h1) - atanf(w2 / h2);
    float v = c4pi2 * dv * dv;
    float alpha = v / (1.f - iou + v + CEPS);
    float ciou = diou - alpha * v;

    float ioum = fmaxf(ciou, 0.f) * ingts;   // pad==1 here
    float score = g_scores_t[((size_t)b * NC + lab) * NL + j];
    float p2 = ioum * ioum;
    float p6 = p2 * p2 * p2;

    g_iou[o] = ioum;
    g_metric[o] = score * p6;
    g_ingts[o] = (unsigned char)ingts;
}

// ---------------- kernel 2: top-13 per (b,gt) with jax tie-break ----------------
__global__ void k_topk(const float* __restrict__ pad) {
    int gt = blockIdx.x;
    if (pad[gt] == 0.f) return;
    const float* row = g_metric + (size_t)gt * NL;
    int t = threadIdx.x;

    unsigned long long best[KTOP];
#pragma unroll
    for (int k = 0; k < KTOP; k++) best[k] = 0ull;

    for (int j = t; j < NL; j += 256) {
        float v = row[j];
        unsigned int fb = __float_as_uint(v);  // v >= 0 -> monotone in bits
        unsigned long long key = ((unsigned long long)fb << 32) |
                                 (unsigned long long)(0xFFFFFFFFu - (unsigned)j);
        if (key > best[KTOP - 1]) {
            best[KTOP - 1] = key;
#pragma unroll
            for (int q = KTOP - 1; q > 0; q--) {
                if (best[q] > best[q - 1]) {
                    unsigned long long tmp = best[q - 1];
                    best[q - 1] = best[q];
                    best[q] = tmp;
                }
            }
        }
    }

    __shared__ unsigned long long sh[256][KTOP];
#pragma unroll
    for (int k = 0; k < KTOP; k++) sh[t][k] = best[k];
    __syncthreads();

    for (int s = 128; s > 0; s >>= 1) {
        if (t < s) {
            unsigned long long tmp[KTOP];
            int a = 0, c = 0;
#pragma unroll
            for (int k = 0; k < KTOP; k++) {
                unsigned long long va = sh[t][a];
                unsigned long long vb = sh[t + s][c];
                if (va >= vb) { tmp[k] = va; a++; }
                else          { tmp[k] = vb; c++; }
            }
#pragma unroll
            for (int k = 0; k < KTOP; k++) sh[t][k] = tmp[k];
        }
        __syncthreads();
    }
    if (t == 0) {
#pragma unroll
        for (int k = 0; k < KTOP; k++)
            g_topk[gt * KTOP + k] =
                (int)(0xFFFFFFFFu - (unsigned)(sh[0][k] & 0xFFFFFFFFull));
    }
}

// ---------------- kernel 3: scatter topk -> mask (mask = in_gts at topk idx) ----------------
__global__ void k_scatter(const float* __restrict__ pad) {
    int gt = blockIdx.x * blockDim.x + threadIdx.x;
    if (gt >= NB * NGT) return;
    if (pad[gt] == 0.f) return;
    size_t base = (size_t)gt * NL;
#pragma unroll
    for (int k = 0; k < KTOP; k++) {
        int idx = g_topk[gt * KTOP + k];
        g_mask[base + idx] = g_ingts[base + idx];
    }
}

// ---------------- kernel 4: per-anchor column pass ----------------
__global__ void k_col(const int* __restrict__ gt_labels,
                      const float* __restrict__ gt_bboxes,
                      float* __restrict__ out, int out_size) {
    int t = blockIdx.x * blockDim.x + threadIdx.x;
    if (t >= NB * NL) return;
    int b = t / NL;
    int j = t - b * NL;
    size_t colbase = (size_t)b * NGT * NL + j;

    int s = 0, ag = -1;
#pragma unroll 8
    for (int i = 0; i < NGT; i++) {
        unsigned char m = g_mask[colbase + (size_t)i * NL];
        s += m;
        if (m && ag < 0) ag = i;
    }
    if (s > 1) {
        float mx = 0.f;
        for (int i = 0; i < NGT; i++)
            mx = fmaxf(mx, g_iou[colbase + (size_t)i * NL]);
        s = 0; ag = -1;
        for (int i = 0; i < NGT; i++) {
            float io = g_iou[colbase + (size_t)i * NL];
            int m = (io == mx) ? 1 : 0;
            g_mask[colbase + (size_t)i * NL] = (unsigned char)m;
            s += m;
            if (m && ag < 0) ag = i;
        }
    }
    int ag0 = (ag < 0) ? 0 : ag;
    int lab = (s > 0) ? gt_labels[b * NGT + ag0] : NC;
    g_lab[t] = lab;

    const int BL = NB * NL;
    if (t < out_size) out[t] = (float)lab;
    size_t bo = (size_t)BL + (size_t)t * 4;
    if (bo + 3 < (size_t)out_size) {
        float4 bb = ((const float4*)gt_bboxes)[b * NGT + ag0];
        ((float4*)(out + BL))[t] = bb;
    }
    size_t fo = (size_t)85 * BL + t;
    if (fo < (size_t)out_size) out[fo] = (s > 0) ? 1.f : 0.f;
}

// ---------------- kernel 5: row maxima of masked metric / iou ----------------
__global__ void k_rowmax() {
    int gt = blockIdx.x;
    size_t base = (size_t)gt * NL;
    float mM = 0.f, mI = 0.f;
    for (int j = threadIdx.x; j < NL; j += 256) {
        if (g_mask[base + j]) {
            mM = fmaxf(mM, g_metric[base + j]);
            mI = fmaxf(mI, g_iou[base + j]);
        }
    }
    __shared__ float sM[256], sI[256];
    sM[threadIdx.x] = mM; sI[threadIdx.x] = mI;
    __syncthreads();
    for (int s = 128; s > 0; s >>= 1) {
        if (threadIdx.x < s) {
            sM[threadIdx.x] = fmaxf(sM[threadIdx.x], sM[threadIdx.x + s]);
            sI[threadIdx.x] = fmaxf(sI[threadIdx.x], sI[threadIdx.x + s]);
        }
        __syncthreads();
    }
    if (threadIdx.x == 0) {
        g_rowmaxM[gt] = sM[0];
        g_rowmaxI[gt] = sI[0];
    }
}

// ---------------- kernel 6: per-anchor norm ----------------
__global__ void k_norm() {
    int t = blockIdx.x * blockDim.x + threadIdx.x;
    if (t >= NB * NL) return;
    int b = t / NL;
    int j = t - b * NL;
    size_t colbase = (size_t)b * NGT * NL + j;
    float nrm = 0.f;
    for (int i = 0; i < NGT; i++) {
        size_t o = colbase + (size_t)i * NL;
        if (g_mask[o]) {
            int gt = b * NGT + i;
            float term = g_metric[o] / (g_rowmaxM[gt] + FEPS) * g_rowmaxI[gt];
            nrm = fmaxf(nrm, term);
        }
    }
    g_norm[t] = nrm;
}

// ---------------- kernel 7: one-hot * norm scores fill ----------------
__global__ void k_scores(float* __restrict__ out, int out_size) {
    int idx = blockIdx.x * blockDim.x + threadIdx.x;
    if (idx >= NB * NL * NC) return;
    int j = idx / NC;
    int c = idx - j * NC;
    float v = (c == g_lab[j]) ? g_norm[j] : 0.f;
    size_t o = (size_t)5 * NB * NL + idx;
    if (o < (size_t)out_size) out[o] = v;
}

// ---------------- launch ----------------
extern "C" void kernel_launch(void* const* d_in, const int* in_sizes, int n_in,
                              void* d_out, int out_size) {
    const float* pred_scores = (const float*)d_in[0];
    const float* pred_bboxes = (const float*)d_in[1];
    const float* centers     = (const float*)d_in[2];
    const int*   gt_labels   = (const int*)d_in[3];
    const float* gt_bboxes   = (const float*)d_in[4];
    const float* pad         = (const float*)d_in[5];
    float* out = (float*)d_out;

    dim3 tb(32, 32);
    dim3 tg((NL + 31) / 32, (NC + 31) / 32, NB);
    k_transpose<<<tg, tb>>>(pred_scores);

    dim3 pg((NL + 255) / 256, NGT, NB);
    k_pair<<<pg, 256>>>(pred_bboxes, centers, gt_labels, gt_bboxes, pad);

    k_topk<<<NB * NGT, 256>>>(pad);
    k_scatter<<<(NB * NGT + 127) / 128, 128>>>(pad);
    k_col<<<(NB * NL + 255) / 256, 256>>>(gt_labels, gt_bboxes, out, out_size);
    k_rowmax<<<NB * NGT, 256>>>();
    k_norm<<<(NB * NL + 255) / 256, 256>>>();
    k_scores<<<((NB * NL * NC) + 255) / 256, 256>>>(out, out_size);
}

// round 2
// speedup vs baseline: 1.9818x; 1.9818x over previous
#include <cuda_runtime.h>
#include <math.h>
#include <stdint.h>

#define NB 32
#define NL 8400
#define NC 80
#define NGT 64
#define KTOP 13
#define FEPS 1e-9f
#define CEPS 1e-7f
#define BL (NB * NL)

// ---------------- device scratch ----------------
__device__ float g_iou[(size_t)NB * NGT * NL];             // masked iou (pad*in_gts applied)
__device__ float g_metric[(size_t)NB * NGT * NL];          // alignment metric
__device__ unsigned char g_ingts[(size_t)NB * NGT * NL];   // is_in_gts
__device__ unsigned char g_mask[(size_t)NB * NGT * NL];    // mask_positive (pre-fixup)
__device__ unsigned int g_rowmaxM[NB * NGT];               // float bits, >=0
__device__ unsigned int g_rowmaxI[NB * NGT];
__device__ unsigned long long g_posmask[BL];               // per-anchor positive gt bits

// ---------------- kernel 1: per-pair iou / metric / in_gts; zero mask ----------------
// one thread per (b, anchor j), loop over valid gts
__global__ void k_pair(const float* __restrict__ pred_scores,
                       const float* __restrict__ pred_bboxes,
                       const float* __restrict__ centers,
                       const int* __restrict__ gt_labels,
                       const float* __restrict__ gt_bboxes,
                       const float* __restrict__ pad) {
    int b = blockIdx.y;
    int tid = threadIdx.x;
    int j = blockIdx.x * 256 + tid;

    __shared__ float4 sbox[NGT];
    __shared__ int slab[NGT];
    __shared__ float satan[NGT], sarea[NGT];
    __shared__ int scnt;

    if (tid < NGT) {
        float4 gb = ((const float4*)gt_bboxes)[b * NGT + tid];
        sbox[tid] = gb;
        slab[tid] = gt_labels[b * NGT + tid];
        satan[tid] = atanf((gb.z - gb.x) / (gb.w - gb.y));
        sarea[tid] = (gb.z - gb.x) * (gb.w - gb.y);
    }
    if (tid == 0) {
        int c = 0;
        for (int i = 0; i < NGT; i++) c += (pad[b * NGT + i] != 0.f);
        scnt = c;
    }
    if (blockIdx.x == 0 && tid < NGT) {       // zero rowmax accumulators
        g_rowmaxM[b * NGT + tid] = 0u;
        g_rowmaxI[b * NGT + tid] = 0u;
    }
    __syncthreads();
    if (j >= NL) return;

    int cnt = scnt;
    float2 ct = ((const float2*)centers)[j];
    float4 p = ((const float4*)pred_bboxes)[(size_t)b * NL + j];
    float a2 = (p.z - p.x) * (p.w - p.y);
    float at2 = atanf((p.z - p.x) / (p.w - p.y));
    float cx2 = (p.x + p.z) * 0.5f, cy2 = (p.y + p.w) * 0.5f;
    const float* srow = pred_scores + ((size_t)b * NL + j) * NC;
    size_t colbase = ((size_t)b * NGT) * NL + j;
    const float c4pi2 = 4.0f / (float)(M_PI * M_PI);

    for (int i = 0; i < cnt; i++) {
        float4 gb = sbox[i];
        float lt = fminf(fminf(ct.x - gb.x, ct.y - gb.y),
                         fminf(gb.z - ct.x, gb.w - ct.y));
        float ingts = (lt > FEPS) ? 1.f : 0.f;

        float iw = fminf(gb.z, p.z) - fmaxf(gb.x, p.x);
        float ih = fminf(gb.w, p.w) - fmaxf(gb.y, p.y);
        float inter = fmaxf(iw, 0.f) * fmaxf(ih, 0.f);
        float uni = sarea[i] + a2 - inter;
        float iou = inter / uni;
        float cw = fmaxf(gb.z, p.z) - fminf(gb.x, p.x);
        float ch = fmaxf(gb.w, p.w) - fminf(gb.y, p.y);
        cw = fmaxf(cw, 0.f); ch = fmaxf(ch, 0.f);
        float diag2 = cw * cw + ch * ch + CEPS;
        float dx = (gb.x + gb.z) * 0.5f - cx2;
        float dy = (gb.y + gb.w) * 0.5f - cy2;
        float diou = iou - (dx * dx + dy * dy) / diag2;
        float dv = satan[i] - at2;
        float v = c4pi2 * dv * dv;
        float alpha = v / (1.f - iou + v + CEPS);
        float ciou = diou - alpha * v;

        float ioum = fmaxf(ciou, 0.f) * ingts;
        float score = __ldg(srow + slab[i]);
        float p2 = ioum * ioum;
        float p6 = p2 * p2 * p2;

        size_t o = colbase + (size_t)i * NL;
        g_iou[o] = ioum;
        g_metric[o] = score * p6;
        g_ingts[o] = (unsigned char)ingts;
        g_mask[o] = 0;
    }
}

// ---------------- kernel 2: top-13 per (b,gt) + fused scatter ----------------
__global__ void k_topk(const float* __restrict__ pad) {
    int gt = blockIdx.x;
    if (pad[gt] == 0.f) return;
    size_t base = (size_t)gt * NL;
    const float* row = g_metric + base;
    int t = threadIdx.x;

    unsigned long long best[KTOP];
#pragma unroll
    for (int k = 0; k < KTOP; k++) best[k] = 0ull;

    for (int j = t; j < NL; j += 256) {
        float v = row[j];
        unsigned int fb = __float_as_uint(v);  // v >= 0 -> monotone in bits
        unsigned long long key = ((unsigned long long)fb << 32) |
                                 (unsigned long long)(0xFFFFFFFFu - (unsigned)j);
        if (key > best[KTOP - 1]) {
            best[KTOP - 1] = key;
#pragma unroll
            for (int q = KTOP - 1; q > 0; q--) {
                if (best[q] > best[q - 1]) {
                    unsigned long long tmp = best[q - 1];
                    best[q - 1] = best[q];
                    best[q] = tmp;
                }
            }
        }
    }

    __shared__ unsigned long long sh[256][KTOP];
#pragma unroll
    for (int k = 0; k < KTOP; k++) sh[t][k] = best[k];
    __syncthreads();

    for (int s = 128; s > 0; s >>= 1) {
        if (t < s) {
            unsigned long long tmp[KTOP];
            int a = 0, c = 0;
#pragma unroll
            for (int k = 0; k < KTOP; k++) {
                unsigned long long va = sh[t][a];
                unsigned long long vb = sh[t + s][c];
                if (va >= vb) { tmp[k] = va; a++; }
                else          { tmp[k] = vb; c++; }
            }
#pragma unroll
            for (int k = 0; k < KTOP; k++) sh[t][k] = tmp[k];
        }
        __syncthreads();
    }
    if (t < KTOP) {  // fused scatter
        int idx = (int)(0xFFFFFFFFu - (unsigned)(sh[0][t] & 0xFFFFFFFFull));
        g_mask[base + idx] = g_ingts[base + idx];
    }
}

// ---------------- kernel 3: per-anchor column pass + rowmax atomics + outputs ----------------
__global__ void k_col(const int* __restrict__ gt_labels,
                      const float* __restrict__ gt_bboxes,
                      const float* __restrict__ pad,
                      float* __restrict__ out, int out_size) {
    int b = blockIdx.y;
    int tid = threadIdx.x;
    int j = blockIdx.x * 256 + tid;

    __shared__ int slab[NGT];
    __shared__ int scnt;
    if (tid < NGT) slab[tid] = gt_labels[b * NGT + tid];
    if (tid == 0) {
        int c = 0;
        for (int i = 0; i < NGT; i++) c += (pad[b * NGT + i] != 0.f);
        scnt = c;
    }
    __syncthreads();
    if (j >= NL) return;

    int cnt = scnt;
    int t = b * NL + j;
    size_t colbase = ((size_t)b * NGT) * NL + j;

    unsigned long long pm = 0ull;
    int s = 0;
    for (int i = 0; i < cnt; i++) {
        if (g_mask[colbase + (size_t)i * NL]) { pm |= 1ull << i; s++; }
    }
    if (s > 1) {  // replace by is_max_iou
        float mx = 0.f;
        for (int i = 0; i < cnt; i++)
            mx = fmaxf(mx, g_iou[colbase + (size_t)i * NL]);
        pm = 0ull; s = 0;
        for (int i = 0; i < cnt; i++) {
            if (g_iou[colbase + (size_t)i * NL] == mx) { pm |= 1ull << i; s++; }
        }
    }
    g_posmask[t] = pm;

    // row maxima of masked metric / iou via atomics
    unsigned long long q = pm;
    while (q) {
        int i = __ffsll(q) - 1;
        q &= q - 1;
        size_t o = colbase + (size_t)i * NL;
        atomicMax(&g_rowmaxM[b * NGT + i], __float_as_uint(g_metric[o]));
        atomicMax(&g_rowmaxI[b * NGT + i], __float_as_uint(g_iou[o]));
    }

    int ag0 = pm ? (__ffsll(pm) - 1) : 0;
    int lab = (s > 0) ? slab[ag0] : NC;

    if (t < out_size) out[t] = (float)lab;
    size_t bo = (size_t)BL + (size_t)t * 4;
    if (bo + 3 < (size_t)out_size) {
        float4 bb = ((const float4*)gt_bboxes)[b * NGT + ag0];
        ((float4*)(out + BL))[t] = bb;
    }
    size_t fo = (size_t)85 * BL + t;
    if (fo < (size_t)out_size) out[fo] = (s > 0) ? 1.f : 0.f;
}

// ---------------- kernel 4: per-anchor norm + one-hot score fill (fused) ----------------
__global__ void k_normscores(const int* __restrict__ gt_labels,
                             float* __restrict__ out, int out_size) {
    int b = blockIdx.y;
    int tid = threadIdx.x;
    int j = blockIdx.x * 256 + tid;

    __shared__ int slab[NGT];
    __shared__ float snrm[256];
    __shared__ int slabel[256];
    if (tid < NGT) slab[tid] = gt_labels[b * NGT + tid];
    __syncthreads();

    float nrm = 0.f;
    int lab = NC;
    if (j < NL) {
        int t = b * NL + j;
        unsigned long long pm = g_posmask[t];
        size_t colbase = ((size_t)b * NGT) * NL + j;
        if (pm) lab = slab[__ffsll(pm) - 1];
        while (pm) {
            int i = __ffsll(pm) - 1;
            pm &= pm - 1;
            float m = g_metric[colbase + (size_t)i * NL];
            float term = m / (__uint_as_float(g_rowmaxM[b * NGT + i]) + FEPS) *
                         __uint_as_float(g_rowmaxI[b * NGT + i]);
            nrm = fmaxf(nrm, term);
        }
    }
    snrm[tid] = nrm;
    slabel[tid] = lab;
    __syncthreads();

    // cooperative coalesced write of this block's 256*80 score floats
    int j0 = blockIdx.x * 256;
    int nanch = NL - j0; if (nanch > 256) nanch = 256;
    if (nanch <= 0) return;
    size_t base = (size_t)5 * BL + ((size_t)b * NL + j0) * NC;  // floats
    int total4 = nanch * (NC / 4);
    float4* ob = (float4*)(out + base);
    for (int f = tid; f < total4; f += 256) {
        int a = f / (NC / 4);
        int c0 = (f % (NC / 4)) * 4;
        float4 w = {0.f, 0.f, 0.f, 0.f};
        int L = slabel[a];
        if (L >= c0 && L < c0 + 4) ((float*)&w)[L - c0] = snrm[a];
        if (base + (size_t)f * 4 + 3 < (size_t)out_size) ob[f] = w;
    }
}

// ---------------- launch ----------------
extern "C" void kernel_launch(void* const* d_in, const int* in_sizes, int n_in,
                              void* d_out, int out_size) {
    const float* pred_scores = (const float*)d_in[0];
    const float* pred_bboxes = (const float*)d_in[1];
    const float* centers     = (const float*)d_in[2];
    const int*   gt_labels   = (const int*)d_in[3];
    const float* gt_bboxes   = (const float*)d_in[4];
    const float* pad         = (const float*)d_in[5];
    float* out = (float*)d_out;

    dim3 grid2d((NL + 255) / 256, NB);
    k_pair<<<grid2d, 256>>>(pred_scores, pred_bboxes, centers,
                            gt_labels, gt_bboxes, pad);
    k_topk<<<NB * NGT, 256>>>(pad);
    k_col<<<grid2d, 256>>>(gt_labels, gt_bboxes, pad, out, out_size);
    k_normscores<<<grid2d, 256>>>(gt_labels, out, out_size);
}

// round 3
// speedup vs baseline: 3.2179x; 1.6237x over previous
#include <cuda_runtime.h>
#include <math.h>
#include <stdint.h>

#define NB 32
#define NL 8400
#define NC 80
#define NGT 64
#define KTOP 13
#define FEPS 1e-9f
#define CEPS 1e-7f
#define BL (NB * NL)

// ---------------- device scratch ----------------
__device__ float g_iou[(size_t)NB * NGT * NL];     // masked iou
__device__ float g_metric[(size_t)NB * NGT * NL];  // alignment metric
__device__ unsigned int g_rowmaxM[NB * NGT];       // float bits, >=0
__device__ unsigned int g_rowmaxI[NB * NGT];
__device__ unsigned long long g_posmask[BL];       // per-anchor positive gt bits

// ---------------- kernel 1: per-pair iou / metric (early-out); zero posmask ----------------
__global__ void k_pair(const float* __restrict__ pred_scores,
                       const float* __restrict__ pred_bboxes,
                       const float* __restrict__ centers,
                       const int* __restrict__ gt_labels,
                       const float* __restrict__ gt_bboxes,
                       const float* __restrict__ pad) {
    int b = blockIdx.y;
    int tid = threadIdx.x;
    int j = blockIdx.x * 256 + tid;

    __shared__ float4 sbox[NGT];
    __shared__ int slab[NGT];
    __shared__ float satan[NGT], sarea[NGT];
    __shared__ int scnt;

    if (tid < NGT) {
        float4 gb = ((const float4*)gt_bboxes)[b * NGT + tid];
        sbox[tid] = gb;
        slab[tid] = gt_labels[b * NGT + tid];
        satan[tid] = atanf(__fdividef(gb.z - gb.x, gb.w - gb.y));
        sarea[tid] = (gb.z - gb.x) * (gb.w - gb.y);
    }
    if (tid == 0) {
        int c = 0;
        for (int i = 0; i < NGT; i++) c += (pad[b * NGT + i] != 0.f);
        scnt = c;
    }
    if (blockIdx.x == 0 && tid < NGT) {
        g_rowmaxM[b * NGT + tid] = 0u;
        g_rowmaxI[b * NGT + tid] = 0u;
    }
    __syncthreads();
    if (j >= NL) return;

    int cnt = scnt;
    int t = b * NL + j;
    g_posmask[t] = 0ull;

    float2 ct = ((const float2*)centers)[j];
    float4 p = ((const float4*)pred_bboxes)[(size_t)b * NL + j];
    float a2 = (p.z - p.x) * (p.w - p.y);
    float at2 = atanf(__fdividef(p.z - p.x, p.w - p.y));
    float cx2 = (p.x + p.z) * 0.5f, cy2 = (p.y + p.w) * 0.5f;
    const float* srow = pred_scores + ((size_t)b * NL + j) * NC;
    size_t colbase = ((size_t)b * NGT) * NL + j;
    const float c4pi2 = 4.0f / (float)(M_PI * M_PI);

    for (int i = 0; i < cnt; i++) {
        float4 gb = sbox[i];
        float lt = fminf(fminf(ct.x - gb.x, ct.y - gb.y),
                         fminf(gb.z - ct.x, gb.w - ct.y));
        size_t o = colbase + (size_t)i * NL;
        if (lt <= FEPS) {              // center outside gt: everything is zero
            g_iou[o] = 0.f;
            g_metric[o] = 0.f;
            continue;
        }
        float iw = fminf(gb.z, p.z) - fmaxf(gb.x, p.x);
        float ih = fminf(gb.w, p.w) - fmaxf(gb.y, p.y);
        float inter = fmaxf(iw, 0.f) * fmaxf(ih, 0.f);
        float uni = sarea[i] + a2 - inter;
        float iou = __fdividef(inter, uni);
        float cw = fmaxf(gb.z, p.z) - fminf(gb.x, p.x);
        float ch = fmaxf(gb.w, p.w) - fminf(gb.y, p.y);
        cw = fmaxf(cw, 0.f); ch = fmaxf(ch, 0.f);
        float diag2 = cw * cw + ch * ch + CEPS;
        float dx = (gb.x + gb.z) * 0.5f - cx2;
        float dy = (gb.y + gb.w) * 0.5f - cy2;
        float diou = iou - __fdividef(dx * dx + dy * dy, diag2);
        float dv = satan[i] - at2;
        float v = c4pi2 * dv * dv;
        float ciou = diou - __fdividef(v * v, 1.f - iou + v + CEPS);

        float ioum = fmaxf(ciou, 0.f);
        float score = __ldg(srow + slab[i]);
        float p2 = ioum * ioum;
        float p6 = p2 * p2 * p2;
        g_iou[o] = ioum;
        g_metric[o] = score * p6;
    }
}

// ---------------- kernel 2: top-13 per (b,gt), fused scatter via atomicOr ----------------
__global__ void k_topk(const float* __restrict__ pad,
                       const float* __restrict__ centers,
                       const float* __restrict__ gt_bboxes) {
    int gt = blockIdx.x;
    if (pad[gt] == 0.f) return;
    size_t base = (size_t)gt * NL;
    const float4* row4 = (const float4*)(g_metric + base);
    int t = threadIdx.x;

    unsigned long long best[KTOP];
#pragma unroll
    for (int k = 0; k < KTOP; k++) best[k] = 0ull;

    for (int j4 = t; j4 < NL / 4; j4 += 256) {
        float4 v4 = row4[j4];
#pragma unroll
        for (int u = 0; u < 4; u++) {
            float v = ((const float*)&v4)[u];
            unsigned j = (unsigned)(j4 * 4 + u);
            unsigned long long key = ((unsigned long long)__float_as_uint(v) << 32) |
                                     (unsigned long long)(0xFFFFFFFFu - j);
            if (key > best[KTOP - 1]) {
                best[KTOP - 1] = key;
#pragma unroll
                for (int q = KTOP - 1; q > 0; q--) {
                    if (best[q] > best[q - 1]) {
                        unsigned long long tmp = best[q - 1];
                        best[q - 1] = best[q];
                        best[q] = tmp;
                    }
                }
            }
        }
    }

    __shared__ unsigned long long sh[256][KTOP];
#pragma unroll
    for (int k = 0; k < KTOP; k++) sh[t][k] = best[k];
    __syncthreads();

    for (int s = 128; s > 0; s >>= 1) {
        if (t < s) {
            unsigned long long tmp[KTOP];
            int a = 0, c = 0;
#pragma unroll
            for (int k = 0; k < KTOP; k++) {
                unsigned long long va = sh[t][a];
                unsigned long long vb = sh[t + s][c];
                if (va >= vb) { tmp[k] = va; a++; }
                else          { tmp[k] = vb; c++; }
            }
#pragma unroll
            for (int k = 0; k < KTOP; k++) sh[t][k] = tmp[k];
        }
        __syncthreads();
    }
    if (t < KTOP) {  // fused scatter with recomputed in-gts test
        int idx = (int)(0xFFFFFFFFu - (unsigned)(sh[0][t] & 0xFFFFFFFFull));
        int b = gt / NGT, i = gt - b * NGT;
        float2 ct = ((const float2*)centers)[idx];
        float4 gb = ((const float4*)gt_bboxes)[gt];
        float lt = fminf(fminf(ct.x - gb.x, ct.y - gb.y),
                         fminf(gb.z - ct.x, gb.w - ct.y));
        if (lt > FEPS)
            atomicOr(&g_posmask[b * NL + idx], 1ull << i);
    }
}

// ---------------- kernel 3: column fixup + rowmax atomics + scalar outputs ----------------
__global__ void k_col(const int* __restrict__ gt_labels,
                      const float* __restrict__ gt_bboxes,
                      const float* __restrict__ pad,
                      float* __restrict__ out, int out_size) {
    int b = blockIdx.y;
    int tid = threadIdx.x;
    int j = blockIdx.x * 256 + tid;

    __shared__ int slab[NGT];
    __shared__ int scnt;
    if (tid < NGT) slab[tid] = gt_labels[b * NGT + tid];
    if (tid == 0) {
        int c = 0;
        for (int i = 0; i < NGT; i++) c += (pad[b * NGT + i] != 0.f);
        scnt = c;
    }
    __syncthreads();
    if (j >= NL) return;

    int cnt = scnt;
    int t = b * NL + j;
    size_t colbase = ((size_t)b * NGT) * NL + j;

    unsigned long long pm = g_posmask[t];
    int s = __popcll(pm);

    // coalesced column max of iou (all threads; keeps s>1 path warp-coherent)
    float mx = 0.f;
    for (int i = 0; i < cnt; i++)
        mx = fmaxf(mx, g_iou[colbase + (size_t)i * NL]);

    if (s > 1) {  // replace by is_max_iou (L1/L2-hot re-read)
        pm = 0ull;
        for (int i = 0; i < cnt; i++)
            if (g_iou[colbase + (size_t)i * NL] == mx) pm |= 1ull << i;
        s = __popcll(pm);
        g_posmask[t] = pm;
    }

    // row maxima of masked metric / iou via atomics
    unsigned long long q = pm;
    while (q) {
        int i = __ffsll(q) - 1;
        q &= q - 1;
        size_t o = colbase + (size_t)i * NL;
        atomicMax(&g_rowmaxM[b * NGT + i], __float_as_uint(g_metric[o]));
        atomicMax(&g_rowmaxI[b * NGT + i], __float_as_uint(g_iou[o]));
    }

    int ag0 = pm ? (__ffsll(pm) - 1) : 0;
    int lab = (s > 0) ? slab[ag0] : NC;

    if (t < out_size) out[t] = (float)lab;
    size_t bo = (size_t)BL + (size_t)t * 4;
    if (bo + 3 < (size_t)out_size) {
        float4 bb = ((const float4*)gt_bboxes)[b * NGT + ag0];
        ((float4*)(out + BL))[t] = bb;
    }
    size_t fo = (size_t)85 * BL + t;
    if (fo < (size_t)out_size) out[fo] = (s > 0) ? 1.f : 0.f;
}

// ---------------- kernel 4: per-anchor norm + one-hot score fill ----------------
__global__ void k_normscores(const int* __restrict__ gt_labels,
                             float* __restrict__ out, int out_size) {
    int b = blockIdx.y;
    int tid = threadIdx.x;
    int j = blockIdx.x * 256 + tid;

    __shared__ int slab[NGT];
    __shared__ float snrm[256];
    __shared__ int slabel[256];
    if (tid < NGT) slab[tid] = gt_labels[b * NGT + tid];
    __syncthreads();

    float nrm = 0.f;
    int lab = NC;
    if (j < NL) {
        int t = b * NL + j;
        unsigned long long pm = g_posmask[t];
        size_t colbase = ((size_t)b * NGT) * NL + j;
        if (pm) lab = slab[__ffsll(pm) - 1];
        while (pm) {
            int i = __ffsll(pm) - 1;
            pm &= pm - 1;
            float m = g_metric[colbase + (size_t)i * NL];
            float term = __fdividef(m, __uint_as_float(g_rowmaxM[b * NGT + i]) + FEPS) *
                         __uint_as_float(g_rowmaxI[b * NGT + i]);
            nrm = fmaxf(nrm, term);
        }
    }
    snrm[tid] = nrm;
    slabel[tid] = lab;
    __syncthreads();

    int j0 = blockIdx.x * 256;
    int nanch = NL - j0; if (nanch > 256) nanch = 256;
    if (nanch <= 0) return;
    size_t base = (size_t)5 * BL + ((size_t)b * NL + j0) * NC;
    int total4 = nanch * (NC / 4);
    float4* ob = (float4*)(out + base);
    for (int f = tid; f < total4; f += 256) {
        int a = f / (NC / 4);
        int c0 = (f % (NC / 4)) * 4;
        float4 w = {0.f, 0.f, 0.f, 0.f};
        int L = slabel[a];
        if (L >= c0 && L < c0 + 4) ((float*)&w)[L - c0] = snrm[a];
        if (base + (size_t)f * 4 + 3 < (size_t)out_size) ob[f] = w;
    }
}

// ---------------- launch ----------------
extern "C" void kernel_launch(void* const* d_in, const int* in_sizes, int n_in,
                              void* d_out, int out_size) {
    const float* pred_scores = (const float*)d_in[0];
    const float* pred_bboxes = (const float*)d_in[1];
    const float* centers     = (const float*)d_in[2];
    const int*   gt_labels   = (const int*)d_in[3];
    const float* gt_bboxes   = (const float*)d_in[4];
    const float* pad         = (const float*)d_in[5];
    float* out = (float*)d_out;

    dim3 grid2d((NL + 255) / 256, NB);
    k_pair<<<grid2d, 256>>>(pred_scores, pred_bboxes, centers,
                            gt_labels, gt_bboxes, pad);
    k_topk<<<NB * NGT, 256>>>(pad, centers, gt_bboxes);
    k_col<<<grid2d, 256>>>(gt_labels, gt_bboxes, pad, out, out_size);
    k_normscores<<<grid2d, 256>>>(gt_labels, out, out_size);
}

// round 4
// speedup vs baseline: 4.3159x; 1.3412x over previous
#include <cuda_runtime.h>
#include <math.h>
#include <stdint.h>

#define NB 32
#define NL 8400
#define NC 80
#define NGT 64
#define KTOP 13
#define CAP 2048
#define NW 263              /* ceil(8400/32) */
#define FEPS 1e-9f
#define CEPS 1e-7f
#define BL (NB * NL)

// ---------------- device scratch ----------------
__device__ unsigned long long g_ckey[(size_t)NB * NGT * CAP]; // row-sparse candidate keys
__device__ unsigned int g_cnt[NB * NGT];                      // per-row candidate counts
__device__ unsigned int g_colmax[BL];                         // per-anchor max iou bits
__device__ unsigned long long g_posmask[BL];                  // per-anchor positive gt bits
__device__ unsigned int g_rowmaxM[NB * NGT];                  // float bits, >=0
__device__ unsigned int g_rowmaxI[NB * NGT];

// ---- shared noinline math: ONE code body -> bit-identical across kernels ----
__device__ __noinline__ float atan_ratio(float w, float h) {
    return atanf(__fdividef(w, h));
}

__device__ __noinline__ float ciou_clip(float4 gb, float4 p, float gatan, float patan) {
    const float c4pi2 = 4.0f / (float)(M_PI * M_PI);
    float a1 = (gb.z - gb.x) * (gb.w - gb.y);
    float a2 = (p.z - p.x) * (p.w - p.y);
    float iw = fminf(gb.z, p.z) - fmaxf(gb.x, p.x);
    float ih = fminf(gb.w, p.w) - fmaxf(gb.y, p.y);
    float inter = fmaxf(iw, 0.f) * fmaxf(ih, 0.f);
    float uni = a1 + a2 - inter;
    float iou = __fdividef(inter, uni);
    float cw = fmaxf(fmaxf(gb.z, p.z) - fminf(gb.x, p.x), 0.f);
    float ch = fmaxf(fmaxf(gb.w, p.w) - fminf(gb.y, p.y), 0.f);
    float diag2 = cw * cw + ch * ch + CEPS;
    float dx = (gb.x + gb.z) * 0.5f - (p.x + p.z) * 0.5f;
    float dy = (gb.y + gb.w) * 0.5f - (p.y + p.w) * 0.5f;
    float diou = iou - __fdividef(dx * dx + dy * dy, diag2);
    float dv = gatan - patan;
    float v = c4pi2 * dv * dv;
    float ciou = diou - __fdividef(v * v, 1.f - iou + v + CEPS);
    return fmaxf(ciou, 0.f);
}

// ---------------- kernel 0: zero counters ----------------
__global__ void k_init() {
    for (int k = threadIdx.x; k < NB * NGT; k += 256) {
        g_cnt[k] = 0u;
        g_rowmaxM[k] = 0u;
        g_rowmaxI[k] = 0u;
    }
}

// ---------------- kernel 1: sparse candidate emission + per-anchor colmax ----------------
__global__ void __launch_bounds__(256) k_pair(
        const float* __restrict__ pred_scores,
        const float* __restrict__ pred_bboxes,
        const float* __restrict__ centers,
        const int* __restrict__ gt_labels,
        const float* __restrict__ gt_bboxes,
        const float* __restrict__ pad) {
    int b = blockIdx.y;
    int tid = threadIdx.x;
    int j = blockIdx.x * 256 + tid;
    int lane = tid & 31;
    unsigned lmask_lt = (1u << lane) - 1u;

    __shared__ float4 sbox[NGT];
    __shared__ int slab[NGT];
    __shared__ float satan[NGT];
    __shared__ int scnt;

    if (tid < NGT) {
        float4 gb = ((const float4*)gt_bboxes)[b * NGT + tid];
        sbox[tid] = gb;
        slab[tid] = gt_labels[b * NGT + tid];
        satan[tid] = atan_ratio(gb.z - gb.x, gb.w - gb.y);
    }
    if (tid == 0) {
        int c = 0;
        for (int i = 0; i < NGT; i++) c += (pad[b * NGT + i] != 0.f);
        scnt = c;
    }
    __syncthreads();

    int cnt = scnt;
    bool live = (j < NL);
    int jc = live ? j : (NL - 1);

    float2 ct = ((const float2*)centers)[jc];
    float4 p = ((const float4*)pred_bboxes)[(size_t)b * NL + jc];
    float patan = atan_ratio(p.z - p.x, p.w - p.y);
    const float* srow = pred_scores + ((size_t)b * NL + jc) * NC;

    float colmax = 0.f;
    for (int i = 0; i < cnt; i++) {
        float4 gb = sbox[i];
        float lt = fminf(fminf(ct.x - gb.x, ct.y - gb.y),
                         fminf(gb.z - ct.x, gb.w - ct.y));
        bool in = live && (lt > FEPS);
        unsigned m = __ballot_sync(0xFFFFFFFFu, in);
        if (!m) continue;
        float io = 0.f;
        unsigned long long key = 0ull;
        if (in) {
            io = ciou_clip(gb, p, satan[i], patan);
            colmax = fmaxf(colmax, io);
            float score = __ldg(srow + slab[i]);
            float m2 = io * io;
            float m6 = m2 * m2 * m2;
            float metric = score * m6;
            key = ((unsigned long long)__float_as_uint(metric) << 32) |
                  (unsigned long long)(0xFFFFFFFFu - (unsigned)j);
        }
        int row = b * NGT + i;
        int leader = __ffs(m) - 1;
        unsigned base = 0;
        if (lane == leader) base = atomicAdd(&g_cnt[row], (unsigned)__popc(m));
        base = __shfl_sync(0xFFFFFFFFu, base, leader);
        if (in) {
            unsigned pos = base + (unsigned)__popc(m & lmask_lt);
            if (pos < CAP) g_ckey[(size_t)row * CAP + pos] = key;
        }
    }
    if (live) {
        int t = b * NL + j;
        g_colmax[t] = __float_as_uint(colmax);
        g_posmask[t] = 0ull;
    }
}

// ---------------- kernel 2: top-13 per row on compact list + exact zero-fill ----------------
__global__ void __launch_bounds__(256) k_topk(const float* __restrict__ pad) {
    int gt = blockIdx.x;
    if (pad[gt] == 0.f) return;
    int b = gt >> 6;
    int i = gt & 63;
    int t = threadIdx.x;

    __shared__ unsigned long long sh[256][KTOP];
    __shared__ unsigned scand[NW];
    __shared__ unsigned szcand[NW];

    for (int w = t; w < NW; w += 256) { scand[w] = 0u; szcand[w] = 0u; }
    __syncthreads();

    unsigned count = g_cnt[gt];
    if (count > CAP) count = CAP;
    const unsigned long long* keys = g_ckey + (size_t)gt * CAP;

    unsigned long long best[KTOP];
#pragma unroll
    for (int k = 0; k < KTOP; k++) best[k] = 0ull;

    for (unsigned c = t; c < count; c += 256) {
        unsigned long long key = keys[c];
        unsigned j = 0xFFFFFFFFu - (unsigned)(key & 0xFFFFFFFFull);
        atomicOr(&scand[j >> 5], 1u << (j & 31));
        if ((unsigned)(key >> 32) == 0u)
            atomicOr(&szcand[j >> 5], 1u << (j & 31));
        if (key > best[KTOP - 1]) {
            best[KTOP - 1] = key;
#pragma unroll
            for (int q = KTOP - 1; q > 0; q--) {
                if (best[q] > best[q - 1]) {
                    unsigned long long tmp = best[q - 1];
                    best[q - 1] = best[q]; best[q] = tmp;
                }
            }
        }
    }
#pragma unroll
    for (int k = 0; k < KTOP; k++) sh[t][k] = best[k];
    __syncthreads();

    for (int s = 128; s > 0; s >>= 1) {
        if (t < s) {
            unsigned long long tmp[KTOP];
            int a = 0, c = 0;
#pragma unroll
            for (int k = 0; k < KTOP; k++) {
                unsigned long long va = sh[t][a];
                unsigned long long vb = sh[t + s][c];
                if (va >= vb) { tmp[k] = va; a++; }
                else          { tmp[k] = vb; c++; }
            }
#pragma unroll
            for (int k = 0; k < KTOP; k++) sh[t][k] = tmp[k];
        }
        __syncthreads();
    }

    // positive-metric selections emit bits directly
    if (t < KTOP) {
        unsigned long long key = sh[0][t];
        if ((unsigned)(key >> 32) != 0u) {
            unsigned j = 0xFFFFFFFFu - (unsigned)(key & 0xFFFFFFFFull);
            atomicOr(&g_posmask[b * NL + j], 1ull << i);
        }
    }
    __syncthreads();

    if (t == 0) {
        int P = 0;
#pragma unroll
        for (int k = 0; k < KTOP; k++)
            if ((unsigned)(sh[0][k] >> 32) != 0u) P++;
        int need = KTOP - P;
        // jax fill: smallest indices with metric==0 (candidate-with-zero OR non-candidate);
        // only zero-metric candidates (in_gts=1) contribute mask bits.
        for (int w = 0; w < NW && need > 0; w++) {
            unsigned zm = (~scand[w]) | szcand[w];
            if (w == NW - 1) zm &= 0xFFFFu;  // 8400 = 262*32 + 16
            while (zm && need > 0) {
                int bit = __ffs(zm) - 1;
                zm &= zm - 1;
                need--;
                if ((szcand[w] >> bit) & 1u) {
                    int j = w * 32 + bit;
                    atomicOr(&g_posmask[b * NL + j], 1ull << i);
                }
            }
        }
    }
}

// ---------------- kernel 3: column fixup (recompute) + rowmax atomics + scalar outputs ----------------
__global__ void __launch_bounds__(256) k_col(
        const float* __restrict__ pred_scores,
        const float* __restrict__ pred_bboxes,
        const float* __restrict__ centers,
        const int* __restrict__ gt_labels,
        const float* __restrict__ gt_bboxes,
        const float* __restrict__ pad,
        float* __restrict__ out, int out_size) {
    int b = blockIdx.y;
    int tid = threadIdx.x;
    int j = blockIdx.x * 256 + tid;

    __shared__ float4 sbox[NGT];
    __shared__ int slab[NGT];
    __shared__ float satan[NGT];
    __shared__ int scnt;
    if (tid < NGT) {
        float4 gb = ((const float4*)gt_bboxes)[b * NGT + tid];
        sbox[tid] = gb;
        slab[tid] = gt_labels[b * NGT + tid];
        satan[tid] = atan_ratio(gb.z - gb.x, gb.w - gb.y);
    }
    if (tid == 0) {
        int c = 0;
        for (int i = 0; i < NGT; i++) c += (pad[b * NGT + i] != 0.f);
        scnt = c;
    }
    __syncthreads();
    if (j >= NL) return;

    int cnt = scnt;
    int t = b * NL + j;
    unsigned long long pm = g_posmask[t];
    int s = __popcll(pm);

    float2 ct = ((const float2*)centers)[j];
    float4 p = ((const float4*)pred_bboxes)[(size_t)b * NL + j];
    float patan = atan_ratio(p.z - p.x, p.w - p.y);
    const float* srow = pred_scores + ((size_t)b * NL + j) * NC;

    if (s > 1) {
        float mx = __uint_as_float(g_colmax[t]);
        if (mx == 0.f) {
            pm = 1ull;              // all-zero column: argmax=0, all terms zero downstream
        } else {
            pm = 0ull;
            for (int i = 0; i < cnt; i++) {
                float4 gb = sbox[i];
                float lt = fminf(fminf(ct.x - gb.x, ct.y - gb.y),
                                 fminf(gb.z - ct.x, gb.w - ct.y));
                if (lt > FEPS) {
                    float io = ciou_clip(gb, p, satan[i], patan);
                    if (io == mx) pm |= 1ull << i;
                }
            }
        }
        s = __popcll(pm);
        g_posmask[t] = pm;
    }

    // rowmax over positives (recompute iou/metric per set bit)
    unsigned long long q = pm;
    while (q) {
        int i = __ffsll(q) - 1;
        q &= q - 1;
        float4 gb = sbox[i];
        float lt = fminf(fminf(ct.x - gb.x, ct.y - gb.y),
                         fminf(gb.z - ct.x, gb.w - ct.y));
        float io = 0.f, metric = 0.f;
        if (lt > FEPS) {
            io = ciou_clip(gb, p, satan[i], patan);
            float score = __ldg(srow + slab[i]);
            float m2 = io * io;
            float m6 = m2 * m2 * m2;
            metric = score * m6;
        }
        atomicMax(&g_rowmaxM[b * NGT + i], __float_as_uint(metric));
        atomicMax(&g_rowmaxI[b * NGT + i], __float_as_uint(io));
    }

    int ag0 = pm ? (__ffsll(pm) - 1) : 0;
    int lab = (s > 0) ? slab[ag0] : NC;

    if (t < out_size) out[t] = (float)lab;
    size_t bo = (size_t)BL + (size_t)t * 4;
    if (bo + 3 < (size_t)out_size) {
        float4 bb = sbox[ag0];
        ((float4*)(out + BL))[t] = bb;
    }
    size_t fo = (size_t)85 * BL + t;
    if (fo < (size_t)out_size) out[fo] = (s > 0) ? 1.f : 0.f;
}

// ---------------- kernel 4: per-anchor norm (recompute) + one-hot score fill ----------------
__global__ void __launch_bounds__(256) k_normscores(
        const float* __restrict__ pred_scores,
        const float* __restrict__ pred_bboxes,
        const float* __restrict__ centers,
        const int* __restrict__ gt_labels,
        const float* __restrict__ gt_bboxes,
        float* __restrict__ out, int out_size) {
    int b = blockIdx.y;
    int tid = threadIdx.x;
    int j = blockIdx.x * 256 + tid;

    __shared__ float4 sbox[NGT];
    __shared__ int slab[NGT];
    __shared__ float satan[NGT];
    __shared__ float snrm[256];
    __shared__ int slabel[256];
    if (tid < NGT) {
        float4 gb = ((const float4*)gt_bboxes)[b * NGT + tid];
        sbox[tid] = gb;
        slab[tid] = gt_labels[b * NGT + tid];
        satan[tid] = atan_ratio(gb.z - gb.x, gb.w - gb.y);
    }
    __syncthreads();

    float nrm = 0.f;
    int lab = NC;
    if (j < NL) {
        int t = b * NL + j;
        unsigned long long pm = g_posmask[t];
        if (pm) {
            lab = slab[__ffsll(pm) - 1];
            float2 ct = ((const float2*)centers)[j];
            float4 p = ((const float4*)pred_bboxes)[(size_t)b * NL + j];
            float patan = atan_ratio(p.z - p.x, p.w - p.y);
            const float* srow = pred_scores + ((size_t)b * NL + j) * NC;
            while (pm) {
                int i = __ffsll(pm) - 1;
                pm &= pm - 1;
                float4 gb = sbox[i];
                float lt = fminf(fminf(ct.x - gb.x, ct.y - gb.y),
                                 fminf(gb.z - ct.x, gb.w - ct.y));
                if (lt > FEPS) {
                    float io = ciou_clip(gb, p, satan[i], patan);
                    float score = __ldg(srow + slab[i]);
                    float m2 = io * io;
                    float m6 = m2 * m2 * m2;
                    float metric = score * m6;
                    float term = __fdividef(metric,
                                     __uint_as_float(g_rowmaxM[b * NGT + i]) + FEPS) *
                                 __uint_as_float(g_rowmaxI[b * NGT + i]);
                    nrm = fmaxf(nrm, term);
                }
            }
        }
    }
    snrm[tid] = nrm;
    slabel[tid] = lab;
    __syncthreads();

    int j0 = blockIdx.x * 256;
    int nanch = NL - j0; if (nanch > 256) nanch = 256;
    if (nanch <= 0) return;
    size_t base = (size_t)5 * BL + ((size_t)b * NL + j0) * NC;
    int total4 = nanch * (NC / 4);
    float4* ob = (float4*)(out + base);
    for (int f = tid; f < total4; f += 256) {
        int a = f / (NC / 4);
        int c0 = (f % (NC / 4)) * 4;
        float4 w = {0.f, 0.f, 0.f, 0.f};
        int L = slabel[a];
        if (L >= c0 && L < c0 + 4) ((float*)&w)[L - c0] = snrm[a];
        if (base + (size_t)f * 4 + 3 < (size_t)out_size) ob[f] = w;
    }
}

// ---------------- launch ----------------
extern "C" void kernel_launch(void* const* d_in, const int* in_sizes, int n_in,
                              void* d_out, int out_size) {
    const float* pred_scores = (const float*)d_in[0];
    const float* pred_bboxes = (const float*)d_in[1];
    const float* centers     = (const float*)d_in[2];
    const int*   gt_labels   = (const int*)d_in[3];
    const float* gt_bboxes   = (const float*)d_in[4];
    const float* pad         = (const float*)d_in[5];
    float* out = (float*)d_out;

    dim3 grid2d((NL + 255) / 256, NB);
    k_init<<<1, 256>>>();
    k_pair<<<grid2d, 256>>>(pred_scores, pred_bboxes, centers,
                            gt_labels, gt_bboxes, pad);
    k_topk<<<NB * NGT, 256>>>(pad);
    k_col<<<grid2d, 256>>>(pred_scores, pred_bboxes, centers,
                           gt_labels, gt_bboxes, pad, out, out_size);
    k_normscores<<<grid2d, 256>>>(pred_scores, pred_bboxes, centers,
                                  gt_labels, gt_bboxes, out, out_size);
}